// round 12
// baseline (speedup 1.0000x reference)
#include <cuda_runtime.h>
#include <cuda_bf16.h>
#include <cstdint>

#define BATCH 16
#define SEQ   2048
#define DIM   128
#define NT    256
#define KPAD  136   // bf16 row stride (272 B) for staged tiles; conflict-free ldmatrix

typedef __nv_bfloat16 bf16;

// Scratch (static device globals; no runtime allocs)
__device__ float g_rowsum[BATCH * SEQ];
__device__ float g_E[(size_t)BATCH * SEQ * SEQ];
__device__ bf16  gQhi[(size_t)BATCH * SEQ * DIM];
__device__ bf16  gQlo[(size_t)BATCH * SEQ * DIM];
__device__ bf16  gKhi[(size_t)BATCH * SEQ * DIM];   // pre-scaled by 1/sqrt(d)
__device__ bf16  gKlo[(size_t)BATCH * SEQ * DIM];
__device__ bf16  gVhi[(size_t)BATCH * SEQ * DIM];
__device__ bf16  gVlo[(size_t)BATCH * SEQ * DIM];

__device__ __forceinline__ void mma16816(float d[4], const uint32_t a[4],
                                         uint32_t b0, uint32_t b1) {
    asm volatile(
        "mma.sync.aligned.m16n8k16.row.col.f32.bf16.bf16.f32 "
        "{%0,%1,%2,%3}, {%4,%5,%6,%7}, {%8,%9}, {%0,%1,%2,%3};\n"
        : "+f"(d[0]), "+f"(d[1]), "+f"(d[2]), "+f"(d[3])
        : "r"(a[0]), "r"(a[1]), "r"(a[2]), "r"(a[3]), "r"(b0), "r"(b1));
}

__device__ __forceinline__ void ldsm4(uint32_t* r, uint32_t addr) {
    asm volatile("ldmatrix.sync.aligned.m8n8.x4.shared.b16 {%0,%1,%2,%3}, [%4];\n"
                 : "=r"(r[0]), "=r"(r[1]), "=r"(r[2]), "=r"(r[3]) : "r"(addr));
}
__device__ __forceinline__ void ldsm4t(uint32_t* r, uint32_t addr) {
    asm volatile("ldmatrix.sync.aligned.m8n8.x4.trans.shared.b16 {%0,%1,%2,%3}, [%4];\n"
                 : "=r"(r[0]), "=r"(r[1]), "=r"(r[2]), "=r"(r[3]) : "r"(addr));
}

__device__ __forceinline__ void cpa16(uint32_t dst, const void* src) {
    asm volatile("cp.async.cg.shared.global [%0], [%1], 16;" :: "r"(dst), "l"(src));
}
#define CPA_COMMIT() asm volatile("cp.async.commit_group;" ::: "memory")
#define CPA_WAIT0()  asm volatile("cp.async.wait_group 0;" ::: "memory")

__device__ __forceinline__ uint32_t bits(__nv_bfloat162 x) {
    return *reinterpret_cast<uint32_t*>(&x);
}

__device__ __forceinline__ void split4(float4 v, uint2& hi, uint2& lo) {
    __nv_bfloat162 h0 = __float22bfloat162_rn(make_float2(v.x, v.y));
    __nv_bfloat162 h1 = __float22bfloat162_rn(make_float2(v.z, v.w));
    float2 f0 = __bfloat1622float2(h0), f1 = __bfloat1622float2(h1);
    __nv_bfloat162 l0 = __float22bfloat162_rn(make_float2(v.x - f0.x, v.y - f0.y));
    __nv_bfloat162 l1 = __float22bfloat162_rn(make_float2(v.z - f1.x, v.w - f1.y));
    hi.x = bits(h0); hi.y = bits(h1);
    lo.x = bits(l0); lo.y = bits(l1);
}

// ---------- prepass: fp32 -> bf16 hi/lo (optional scale) ----------
__global__ void split_kernel(const float* __restrict__ src, bf16* __restrict__ hi,
                             bf16* __restrict__ lo, float scale) {
    size_t i = ((size_t)blockIdx.x * NT + threadIdx.x) * 4;
    float4 v = *(const float4*)(src + i);
    v.x *= scale; v.y *= scale; v.z *= scale; v.w *= scale;
    uint2 h, l; split4(v, h, l);
    *(uint2*)(hi + i) = h;
    *(uint2*)(lo + i) = l;
}

// ============================================================================
// Kernel 1: per CTA, i-tile pair {itp, 15-itp}; E = exp(mask(K*Q^T)) -> gmem,
// rowsums in registers. Q tiles cp.async DOUBLE-BUFFERED (ping-pong).
// Grid (8 pairs, 16 b) = 128 CTAs. 1 CTA/SM.
// smem: sKhi/lo [128][136] + 2x sQhi/lo [128][136] + srow = 209408 B
// ============================================================================
__global__ void __launch_bounds__(NT, 1)
scores_strip_kernel(float* __restrict__ outW)
{
    extern __shared__ char sm1[];
    // layout: Khi@0 Klo@34816 Q0hi@69632 Q0lo@104448 Q1hi@139264 Q1lo@174080 srow@208896
    float* srow = (float*)(sm1 + 208896);
    const uint32_t sbase = (uint32_t)__cvta_generic_to_shared(sm1);

    const int itp = blockIdx.x, b = blockIdx.y;
    const int tid = threadIdx.x;
    const int w = tid >> 5, lane = tid & 31;
    const int mw = w >> 2, nw = w & 3;
    const int rb = mw * 64, cb = nw * 32;

    const int laneAr = lane & 15;
    const int laneAk = (lane & 16) >> 1;
    const int laneBr = (lane & 7) | ((lane & 16) >> 1);
    const int laneBk = lane & 8;

    const uint32_t aHb = sbase + ((rb + laneAr) * KPAD + laneAk) * 2;
    const uint32_t aLb = aHb + 34816;
    const uint32_t bOff = ((cb + laneBr) * KPAD + laneBk) * 2;

    const int g = lane >> 2, q = lane & 3;

    // cp.async staging coords: row = tid>>1, col half = tid&1
    const int srow_c = tid >> 1;
    const int chalf  = tid & 1;
    const uint32_t sdst = srow_c * 272 + chalf * 128;   // byte offset within a tile
    const int gsrc = srow_c * DIM + chalf * 64;         // element offset

    #pragma unroll 1
    for (int half = 0; half < 2; ++half) {
        const int it = (half == 0) ? itp : 15 - itp;
        const int i0 = it * 128;

        // stage K tile (pre-scaled, pre-split) via cp.async
        {
            const bf16* Kh = gKhi + ((size_t)b * SEQ + i0) * DIM;
            const bf16* Kl = gKlo + ((size_t)b * SEQ + i0) * DIM;
            #pragma unroll
            for (int c = 0; c < 8; ++c) {
                cpa16(sbase + sdst + c * 16,         Kh + gsrc + c * 8);
                cpa16(sbase + 34816 + sdst + c * 16, Kl + gsrc + c * 8);
            }
            CPA_COMMIT();
        }
        if (tid < 128) srow[tid] = 0.0f;

        // zero-fill masked W prefix: rows [i0,i0+128), cols [0,i0)
        if (i0 > 0) {
            float4 z = make_float4(0.f, 0.f, 0.f, 0.f);
            float* Wp = outW + ((size_t)b * SEQ + i0) * SEQ;
            const int c4n = i0 >> 2;
            const int total = 128 * c4n;
            for (int x = tid; x < total; x += NT) {
                int row = x / c4n, c = (x - row * c4n) * 4;
                *(float4*)(Wp + (size_t)row * SEQ + c) = z;
            }
        }

        // prologue: stage Q(it) into buffer 0
        {
            const bf16* Qh = gQhi + ((size_t)b * SEQ + i0) * DIM;
            const bf16* Ql = gQlo + ((size_t)b * SEQ + i0) * DIM;
            #pragma unroll
            for (int c = 0; c < 8; ++c) {
                cpa16(sbase + 69632 + sdst + c * 16,  Qh + gsrc + c * 8);
                cpa16(sbase + 104448 + sdst + c * 16, Ql + gsrc + c * 8);
            }
            CPA_COMMIT();
        }

        float rsum[8];
        #pragma unroll
        for (int k = 0; k < 8; ++k) rsum[k] = 0.f;

        float* Ep = g_E + (size_t)b * SEQ * SEQ;

        for (int jt = it; jt < 16; ++jt) {
            const int j0 = jt * 128;
            const int buf = (jt - it) & 1;

            CPA_WAIT0();
            __syncthreads();

            // stage next Q into the other buffer (overlaps MMA below)
            if (jt + 1 < 16) {
                const uint32_t qb = 69632 + (buf ^ 1) * 69632;
                const bf16* Qh = gQhi + ((size_t)b * SEQ + j0 + 128) * DIM;
                const bf16* Ql = gQlo + ((size_t)b * SEQ + j0 + 128) * DIM;
                #pragma unroll
                for (int c = 0; c < 8; ++c) {
                    cpa16(sbase + qb + sdst + c * 16,         Qh + gsrc + c * 8);
                    cpa16(sbase + qb + 34816 + sdst + c * 16, Ql + gsrc + c * 8);
                }
                CPA_COMMIT();
            }

            const uint32_t bHb = sbase + 69632 + buf * 69632 + bOff;
            const uint32_t bLb = bHb + 34816;

            float acc[4][4][4];
            #pragma unroll
            for (int a = 0; a < 4; ++a)
                #pragma unroll
                for (int c = 0; c < 4; ++c)
                    #pragma unroll
                    for (int d = 0; d < 4; ++d) acc[a][c][d] = 0.f;

            #pragma unroll
            for (int ks = 0; ks < 8; ++ks) {
                uint32_t bh[8], bl[8];
                ldsm4(bh,     bHb + ks * 32);
                ldsm4(bh + 4, bHb + 16 * KPAD * 2 + ks * 32);
                ldsm4(bl,     bLb + ks * 32);
                ldsm4(bl + 4, bLb + 16 * KPAD * 2 + ks * 32);
                #pragma unroll
                for (int mf = 0; mf < 4; ++mf) {
                    uint32_t ah[4], al[4];
                    ldsm4(ah, aHb + mf * 16 * KPAD * 2 + ks * 32);
                    ldsm4(al, aLb + mf * 16 * KPAD * 2 + ks * 32);
                    #pragma unroll
                    for (int nf = 0; nf < 4; ++nf) {
                        mma16816(acc[mf][nf], ah, bh[2 * nf], bh[2 * nf + 1]);
                        mma16816(acc[mf][nf], ah, bl[2 * nf], bl[2 * nf + 1]);
                        mma16816(acc[mf][nf], al, bh[2 * nf], bh[2 * nf + 1]);
                    }
                }
            }

            // epilogue: exp + mask (diag only), store E, accumulate rowsums
            const bool diag = (jt == it);
            #pragma unroll
            for (int mf = 0; mf < 4; ++mf) {
                int r0 = i0 + rb + mf * 16 + g;
                int r1 = r0 + 8;
                float s0 = 0.f, s1 = 0.f;
                #pragma unroll
                for (int nf = 0; nf < 4; ++nf) {
                    int c = j0 + cb + nf * 8 + q * 2;
                    float e00 = __expf(acc[mf][nf][0]);
                    float e01 = __expf(acc[mf][nf][1]);
                    float e10 = __expf(acc[mf][nf][2]);
                    float e11 = __expf(acc[mf][nf][3]);
                    if (diag) {
                        if (c     < r0) e00 = 0.f;
                        if (c + 1 < r0) e01 = 0.f;
                        if (c     < r1) e10 = 0.f;
                        if (c + 1 < r1) e11 = 0.f;
                    }
                    s0 += e00 + e01; s1 += e10 + e11;
                    *(float2*)(Ep + (size_t)r0 * SEQ + c) = make_float2(e00, e01);
                    *(float2*)(Ep + (size_t)r1 * SEQ + c) = make_float2(e10, e11);
                }
                rsum[mf * 2]     += s0;
                rsum[mf * 2 + 1] += s1;
            }
        }

        __syncthreads();
        // reduce rowsums: quad shuffle then one smem atomic per (warp,row)
        #pragma unroll
        for (int k = 0; k < 8; ++k) {
            float s = rsum[k];
            s += __shfl_xor_sync(0xffffffffu, s, 1);
            s += __shfl_xor_sync(0xffffffffu, s, 2);
            if (q == 0) {
                int mf = k >> 1;
                int row = rb + mf * 16 + g + (k & 1) * 8;
                atomicAdd(&srow[row], s);
            }
        }
        __syncthreads();
        if (tid < 128) g_rowsum[b * SEQ + i0 + tid] = srow[tid];
        __syncthreads();   // srow/sK reuse safety for next half
    }
}

// ============================================================================
// Kernel 2: W = E/rowsum (write), O = W*V. Row-split (64 i-rows x D=128 per
// CTA). V staged from pre-split bf16 via cp.async issued BEFORE the W staging
// section (overlap); E register prefetch overlaps MMA. Diagonal-paired.
// Grid (2 rh, 8 pairs, 16 b) = 256 CTAs; 2 CTA/SM.
// smem: sWhi/lo [64][136] + sVhi/lo [128][136] + sInv[64] = 104704 B
// ============================================================================
__global__ void __launch_bounds__(NT, 2)
output_kernel(float* __restrict__ outO, float* __restrict__ outW)
{
    extern __shared__ char sm2[];
    __nv_bfloat16* sWhi = (__nv_bfloat16*)(sm2);
    __nv_bfloat16* sWlo = (__nv_bfloat16*)(sm2 + 17408);
    float*         sInv = (float*)(sm2 + 104448);
    const uint32_t sbase = (uint32_t)__cvta_generic_to_shared(sm2);
    const uint32_t svhi = sbase + 34816;   // V hi @34816, V lo @69632

    const int rh = blockIdx.x, itp = blockIdx.y, b = blockIdx.z;
    const int tid = threadIdx.x;
    const int w = tid >> 5, lane = tid & 31;
    const int mw = w >> 2, nw = w & 3;
    const int rb = mw * 32, cb = nw * 32;   // 64 rows, 128 d-cols per CTA

    const int laneAr = lane & 15;
    const int laneAk = (lane & 16) >> 1;
    const int laneTr = lane & 15;
    const int laneTd = (lane & 16) >> 1;

    const uint32_t aHb = sbase + ((rb + laneAr) * KPAD + laneAk) * 2;
    const uint32_t aLb = aHb + 17408;
    const uint32_t bHb = svhi + (laneTr * KPAD + cb + laneTd) * 2;
    const uint32_t bLb = bHb + 34816;

    const float* Ep = g_E + (size_t)b * SEQ * SEQ;
    float* Wp = outW + (size_t)b * SEQ * SEQ;
    const int g = lane >> 2, q = lane & 3;

    const int erow = tid >> 5;           // + i*8, i<8
    const int ec4  = (tid & 31) * 4;
    // V cp.async coords
    const int vrow = tid >> 1;
    const int vhalf = tid & 1;
    const uint32_t vdst = vrow * 272 + vhalf * 128;
    const int vsrc = vrow * DIM + vhalf * 64;

    #pragma unroll 1
    for (int half = 0; half < 2; ++half) {
        const int it = (half == 0) ? itp : 15 - itp;
        const int i0 = it * 128;
        const int i0g = i0 + rh * 64;    // this CTA's first row

        if (tid < 64) sInv[tid] = 1.0f / g_rowsum[b * SEQ + i0g + tid];

        float acc[2][4][4];
        #pragma unroll
        for (int a = 0; a < 2; ++a)
            #pragma unroll
            for (int c = 0; c < 4; ++c)
                #pragma unroll
                for (int d = 0; d < 4; ++d) acc[a][c][d] = 0.f;

        // prefetch first E tile (8 float4/thread)
        float4 epre[8];
        #pragma unroll
        for (int i = 0; i < 8; ++i)
            epre[i] = *(const float4*)(Ep + (size_t)(i0g + erow + i * 8) * SEQ +
                                       it * 128 + ec4);
        __syncthreads();

        for (int jt = it; jt < 16; ++jt) {
            const int j0 = jt * 128;

            // issue V tile cp.async first: transfer overlaps the W staging below
            {
                const bf16* Vh = gVhi + ((size_t)b * SEQ + j0) * DIM;
                const bf16* Vl = gVlo + ((size_t)b * SEQ + j0) * DIM;
                #pragma unroll
                for (int c = 0; c < 8; ++c) {
                    cpa16(svhi + vdst + c * 16,         Vh + vsrc + c * 8);
                    cpa16(svhi + 34816 + vdst + c * 16, Vl + vsrc + c * 8);
                }
                CPA_COMMIT();
            }

            // stage normalized weights from prefetch regs; write W
            #pragma unroll
            for (int i = 0; i < 8; ++i) {
                int row = erow + i * 8;
                float4 v = epre[i];
                float inv = sInv[row];
                v.x *= inv; v.y *= inv; v.z *= inv; v.w *= inv;
                *(float4*)(Wp + (size_t)(i0g + row) * SEQ + j0 + ec4) = v;
                uint2 hi, lo; split4(v, hi, lo);
                *(uint2*)(sWhi + row * KPAD + ec4) = hi;
                *(uint2*)(sWlo + row * KPAD + ec4) = lo;
            }
            CPA_WAIT0();
            __syncthreads();

            // prefetch next E tile: overlaps with MMA below
            if (jt + 1 < 16) {
                #pragma unroll
                for (int i = 0; i < 8; ++i)
                    epre[i] = *(const float4*)(Ep + (size_t)(i0g + erow + i * 8) * SEQ +
                                               j0 + 128 + ec4);
            }

            #pragma unroll
            for (int ks = 0; ks < 8; ++ks) {
                uint32_t bh[8], bl[8];
                ldsm4t(bh,     bHb + ks * 16 * KPAD * 2);
                ldsm4t(bh + 4, bHb + ks * 16 * KPAD * 2 + 32);   // d-cols +16
                ldsm4t(bl,     bLb + ks * 16 * KPAD * 2);
                ldsm4t(bl + 4, bLb + ks * 16 * KPAD * 2 + 32);
                #pragma unroll
                for (int mf = 0; mf < 2; ++mf) {
                    uint32_t ah[4], al[4];
                    ldsm4(ah, aHb + mf * 16 * KPAD * 2 + ks * 32);
                    ldsm4(al, aLb + mf * 16 * KPAD * 2 + ks * 32);
                    #pragma unroll
                    for (int nf = 0; nf < 4; ++nf) {
                        mma16816(acc[mf][nf], ah, bh[2 * nf], bh[2 * nf + 1]);
                        mma16816(acc[mf][nf], ah, bl[2 * nf], bl[2 * nf + 1]);
                        mma16816(acc[mf][nf], al, bh[2 * nf], bh[2 * nf + 1]);
                    }
                }
            }
            __syncthreads();
        }

        // epilogue: write O for this CTA's 64 rows
        #pragma unroll
        for (int mf = 0; mf < 2; ++mf) {
            int r0 = i0g + rb + mf * 16 + g;
            int r1 = r0 + 8;
            #pragma unroll
            for (int nf = 0; nf < 4; ++nf) {
                int c = cb + nf * 8 + q * 2;
                *(float2*)(outO + ((size_t)b * SEQ + r0) * DIM + c) =
                    make_float2(acc[mf][nf][0], acc[mf][nf][1]);
                *(float2*)(outO + ((size_t)b * SEQ + r1) * DIM + c) =
                    make_float2(acc[mf][nf][2], acc[mf][nf][3]);
            }
        }
        __syncthreads();   // sInv/sW reuse safety for next half
    }
}

extern "C" void kernel_launch(void* const* d_in, const int* in_sizes, int n_in,
                              void* d_out, int out_size)
{
    const float* Q = (const float*)d_in[0];
    const float* K = (const float*)d_in[1];
    const float* V = (const float*)d_in[2];
    float* out  = (float*)d_out;
    float* outO = out;                               // (B,S,D)
    float* outW = out + (size_t)BATCH * SEQ * DIM;   // (B,S,S)

    static int attr_done = 0;
    if (!attr_done) {
        cudaFuncSetAttribute(scores_strip_kernel,
                             cudaFuncAttributeMaxDynamicSharedMemorySize, 209408);
        cudaFuncSetAttribute(output_kernel,
                             cudaFuncAttributeMaxDynamicSharedMemorySize, 104704);
        attr_done = 1;
    }

    const float scale = 0.08838834764831845f;  // 1/sqrt(128)
    const int nsplit = (BATCH * SEQ * DIM) / (4 * NT);   // 4096

    bf16 *pQhi, *pQlo, *pKhi, *pKlo, *pVhi, *pVlo;
    cudaGetSymbolAddress((void**)&pQhi, gQhi);
    cudaGetSymbolAddress((void**)&pQlo, gQlo);
    cudaGetSymbolAddress((void**)&pKhi, gKhi);
    cudaGetSymbolAddress((void**)&pKlo, gKlo);
    cudaGetSymbolAddress((void**)&pVhi, gVhi);
    cudaGetSymbolAddress((void**)&pVlo, gVlo);

    split_kernel<<<nsplit, NT>>>(Q, pQhi, pQlo, 1.0f);
    split_kernel<<<nsplit, NT>>>(K, pKhi, pKlo, scale);
    split_kernel<<<nsplit, NT>>>(V, pVhi, pVlo, 1.0f);

    scores_strip_kernel<<<dim3(8, 16), NT, 209408>>>(outW);
    output_kernel<<<dim3(2, 8, 16), NT, 104704>>>(outO, outW);
}

// round 13
// speedup vs baseline: 1.2294x; 1.2294x over previous
#include <cuda_runtime.h>
#include <cuda_bf16.h>
#include <cstdint>

#define BATCH 16
#define SEQ   2048
#define DIM   128
#define NT    256
#define KPAD  136   // bf16 row stride for 128-wide tiles (conflict-free ldmatrix)

// Scratch: raw exp(scores) + per-row sums. __device__ globals (no allocs allowed).
__device__ float g_rowsum[BATCH * SEQ];
__device__ float g_E[(size_t)BATCH * SEQ * SEQ];

__device__ __forceinline__ void mma16816(float d[4], const uint32_t a[4],
                                         uint32_t b0, uint32_t b1) {
    asm volatile(
        "mma.sync.aligned.m16n8k16.row.col.f32.bf16.bf16.f32 "
        "{%0,%1,%2,%3}, {%4,%5,%6,%7}, {%8,%9}, {%0,%1,%2,%3};\n"
        : "+f"(d[0]), "+f"(d[1]), "+f"(d[2]), "+f"(d[3])
        : "r"(a[0]), "r"(a[1]), "r"(a[2]), "r"(a[3]), "r"(b0), "r"(b1));
}

__device__ __forceinline__ void ldsm4(uint32_t* r, uint32_t addr) {
    asm volatile("ldmatrix.sync.aligned.m8n8.x4.shared.b16 {%0,%1,%2,%3}, [%4];\n"
                 : "=r"(r[0]), "=r"(r[1]), "=r"(r[2]), "=r"(r[3]) : "r"(addr));
}
__device__ __forceinline__ void ldsm4t(uint32_t* r, uint32_t addr) {
    asm volatile("ldmatrix.sync.aligned.m8n8.x4.trans.shared.b16 {%0,%1,%2,%3}, [%4];\n"
                 : "=r"(r[0]), "=r"(r[1]), "=r"(r[2]), "=r"(r[3]) : "r"(addr));
}

__device__ __forceinline__ uint32_t bits(__nv_bfloat162 x) {
    return *reinterpret_cast<uint32_t*>(&x);
}

// fp32x4 -> bf16 hi quad + bf16 lo quad
__device__ __forceinline__ void split4(float4 v, uint2& hi, uint2& lo) {
    __nv_bfloat162 h0 = __float22bfloat162_rn(make_float2(v.x, v.y));
    __nv_bfloat162 h1 = __float22bfloat162_rn(make_float2(v.z, v.w));
    float2 f0 = __bfloat1622float2(h0), f1 = __bfloat1622float2(h1);
    __nv_bfloat162 l0 = __float22bfloat162_rn(make_float2(v.x - f0.x, v.y - f0.y));
    __nv_bfloat162 l1 = __float22bfloat162_rn(make_float2(v.z - f1.x, v.w - f1.y));
    hi.x = bits(h0); hi.y = bits(h1);
    lo.x = bits(l0); lo.y = bits(l1);
}

// ============================================================================
// Kernel 1 (strip form): per CTA, i-tile pair {itp, 15-itp}; for each i-tile,
// loop jt=it..15: E = exp(mask(K*Q^T/sqrt(d))) -> gmem, rowsums in registers.
// FULL next-Q-tile register prefetch (16 float4) overlaps all Q LDG with MMA.
// Grid (8 pairs, 16 b) = 128 CTAs -> single wave, 17 GEMMs each.
// smem: sKhi/lo, sQhi/lo [128][136] bf16 + srow[128] = 139776 B
// ============================================================================
__global__ void __launch_bounds__(NT, 1)
scores_strip_kernel(const float* __restrict__ Q, const float* __restrict__ K,
                    float* __restrict__ outW)
{
    extern __shared__ char sm1[];
    __nv_bfloat16* sKhi = (__nv_bfloat16*)(sm1);
    __nv_bfloat16* sKlo = (__nv_bfloat16*)(sm1 + 34816);
    __nv_bfloat16* sQhi = (__nv_bfloat16*)(sm1 + 69632);
    __nv_bfloat16* sQlo = (__nv_bfloat16*)(sm1 + 104448);
    float*         srow = (float*)(sm1 + 139264);

    const int itp = blockIdx.x, b = blockIdx.y;
    const int tid = threadIdx.x;
    const int w = tid >> 5, lane = tid & 31;
    const int mw = w >> 2, nw = w & 3;
    const int rb = mw * 64, cb = nw * 32;

    const int laneAr = lane & 15;
    const int laneAk = (lane & 16) >> 1;
    const int laneBr = (lane & 7) | ((lane & 16) >> 1);
    const int laneBk = lane & 8;

    const uint32_t aHb = (uint32_t)__cvta_generic_to_shared(sKhi) +
                         ((rb + laneAr) * KPAD + laneAk) * 2;
    const uint32_t aLb = (uint32_t)__cvta_generic_to_shared(sKlo) +
                         ((rb + laneAr) * KPAD + laneAk) * 2;
    const uint32_t bHb = (uint32_t)__cvta_generic_to_shared(sQhi) +
                         ((cb + laneBr) * KPAD + laneBk) * 2;
    const uint32_t bLb = (uint32_t)__cvta_generic_to_shared(sQlo) +
                         ((cb + laneBr) * KPAD + laneBk) * 2;

    const float scale = 0.08838834764831845f;   // 1/sqrt(128)
    const int g = lane >> 2, q = lane & 3;

    // per-thread staging coordinates (row, col4)
    const int prow = tid >> 5;           // rows covered: prow + i*8
    const int pc4  = (tid & 31) * 4;

    #pragma unroll 1
    for (int half = 0; half < 2; ++half) {
        const int it = (half == 0) ? itp : 15 - itp;
        const int i0 = it * 128;
        const float* Qbase = Q + (size_t)b * SEQ * DIM;

        // stage K tile for this strip (scaled, split)
        {
            const float* Kp = K + ((size_t)b * SEQ + i0) * DIM;
            #pragma unroll
            for (int i = 0; i < 16; ++i) {
                int row = prow + i * 8;
                float4 v = *(const float4*)(Kp + row * DIM + pc4);
                v.x *= scale; v.y *= scale; v.z *= scale; v.w *= scale;
                uint2 hi, lo; split4(v, hi, lo);
                *(uint2*)(sKhi + row * KPAD + pc4) = hi;
                *(uint2*)(sKlo + row * KPAD + pc4) = lo;
            }
        }
        if (tid < 128) srow[tid] = 0.0f;

        // zero-fill masked W prefix: rows [i0,i0+128), cols [0,i0)
        if (i0 > 0) {
            float4 z = make_float4(0.f, 0.f, 0.f, 0.f);
            float* Wp = outW + ((size_t)b * SEQ + i0) * SEQ;
            const int c4n = i0 >> 2;
            const int total = 128 * c4n;
            for (int x = tid; x < total; x += NT) {
                int row = x / c4n, c = (x - row * c4n) * 4;
                *(float4*)(Wp + (size_t)row * SEQ + c) = z;
            }
        }

        float rsum[8];
        #pragma unroll
        for (int k = 0; k < 8; ++k) rsum[k] = 0.f;

        float* Ep = g_E + (size_t)b * SEQ * SEQ;

        // prefetch FULL first Q tile into registers
        float4 qpre[16];
        #pragma unroll
        for (int i = 0; i < 16; ++i)
            qpre[i] = *(const float4*)(Qbase + (it * 128 + prow + i * 8) * DIM + pc4);

        for (int jt = it; jt < 16; ++jt) {
            const int j0 = jt * 128;
            // stage Q tile entirely from prefetch regs (no gmem on critical path)
            #pragma unroll
            for (int i = 0; i < 16; ++i) {
                int row = prow + i * 8;
                uint2 hi, lo; split4(qpre[i], hi, lo);
                *(uint2*)(sQhi + row * KPAD + pc4) = hi;
                *(uint2*)(sQlo + row * KPAD + pc4) = lo;
            }
            __syncthreads();

            // prefetch next FULL Q tile: overlaps with MMA below
            if (jt + 1 < 16) {
                const float* Qn = Qbase + (size_t)(j0 + 128) * DIM;
                #pragma unroll
                for (int i = 0; i < 16; ++i)
                    qpre[i] = *(const float4*)(Qn + (prow + i * 8) * DIM + pc4);
            }

            float acc[4][4][4];
            #pragma unroll
            for (int a = 0; a < 4; ++a)
                #pragma unroll
                for (int c = 0; c < 4; ++c)
                    #pragma unroll
                    for (int d = 0; d < 4; ++d) acc[a][c][d] = 0.f;

            #pragma unroll
            for (int ks = 0; ks < 8; ++ks) {
                uint32_t bh[8], bl[8];
                ldsm4(bh,     bHb + ks * 32);
                ldsm4(bh + 4, bHb + 16 * KPAD * 2 + ks * 32);
                ldsm4(bl,     bLb + ks * 32);
                ldsm4(bl + 4, bLb + 16 * KPAD * 2 + ks * 32);
                #pragma unroll
                for (int mf = 0; mf < 4; ++mf) {
                    uint32_t ah[4], al[4];
                    ldsm4(ah, aHb + mf * 16 * KPAD * 2 + ks * 32);
                    ldsm4(al, aLb + mf * 16 * KPAD * 2 + ks * 32);
                    #pragma unroll
                    for (int nf = 0; nf < 4; ++nf) {
                        mma16816(acc[mf][nf], ah, bh[2 * nf], bh[2 * nf + 1]);
                        mma16816(acc[mf][nf], ah, bl[2 * nf], bl[2 * nf + 1]);
                        mma16816(acc[mf][nf], al, bh[2 * nf], bh[2 * nf + 1]);
                    }
                }
            }

            // epilogue: exp + mask (diag tile only), store E, accumulate rowsums
            const bool diag = (jt == it);
            #pragma unroll
            for (int mf = 0; mf < 4; ++mf) {
                int r0 = i0 + rb + mf * 16 + g;
                int r1 = r0 + 8;
                float s0 = 0.f, s1 = 0.f;
                #pragma unroll
                for (int nf = 0; nf < 4; ++nf) {
                    int c = j0 + cb + nf * 8 + q * 2;
                    float e00 = __expf(acc[mf][nf][0]);
                    float e01 = __expf(acc[mf][nf][1]);
                    float e10 = __expf(acc[mf][nf][2]);
                    float e11 = __expf(acc[mf][nf][3]);
                    if (diag) {
                        if (c     < r0) e00 = 0.f;
                        if (c + 1 < r0) e01 = 0.f;
                        if (c     < r1) e10 = 0.f;
                        if (c + 1 < r1) e11 = 0.f;
                    }
                    s0 += e00 + e01; s1 += e10 + e11;
                    *(float2*)(Ep + (size_t)r0 * SEQ + c) = make_float2(e00, e01);
                    *(float2*)(Ep + (size_t)r1 * SEQ + c) = make_float2(e10, e11);
                }
                rsum[mf * 2]     += s0;
                rsum[mf * 2 + 1] += s1;
            }
            __syncthreads();   // protect sQ before next stage
        }

        // reduce rowsums: quad shuffle then one smem atomic per (warp,row)
        #pragma unroll
        for (int k = 0; k < 8; ++k) {
            float s = rsum[k];
            s += __shfl_xor_sync(0xffffffffu, s, 1);
            s += __shfl_xor_sync(0xffffffffu, s, 2);
            if (q == 0) {
                int mf = k >> 1;
                int row = rb + mf * 16 + g + (k & 1) * 8;
                atomicAdd(&srow[row], s);
            }
        }
        __syncthreads();
        if (tid < 128) g_rowsum[b * SEQ + i0 + tid] = srow[tid];
        __syncthreads();   // srow/sK reuse safety for next half
    }
}

// ============================================================================
// Kernel 2: W = E/rowsum (write), O = W*V. Row-split (64 i-rows x full D=128
// per CTA); E register prefetch overlaps LDG with MMA. Diagonal-paired;
// grid (2 row-halves, 8 pairs, 16 b) = 256 CTAs, 17 uniform j-iterations.
// smem: sWhi/lo [64][136] + sVhi/lo [128][136] + sInv[64] = 104704 B -> 2 CTA/SM
// ============================================================================
__global__ void __launch_bounds__(NT, 2)
output_kernel(const float* __restrict__ V, float* __restrict__ outO,
              float* __restrict__ outW)
{
    extern __shared__ char sm2[];
    __nv_bfloat16* sWhi = (__nv_bfloat16*)(sm2);
    __nv_bfloat16* sWlo = (__nv_bfloat16*)(sm2 + 17408);
    __nv_bfloat16* sVhi = (__nv_bfloat16*)(sm2 + 34816);
    __nv_bfloat16* sVlo = (__nv_bfloat16*)(sm2 + 69632);
    float*         sInv = (float*)(sm2 + 104448);

    const int rh = blockIdx.x, itp = blockIdx.y, b = blockIdx.z;
    const int tid = threadIdx.x;
    const int w = tid >> 5, lane = tid & 31;
    const int mw = w >> 2, nw = w & 3;
    const int rb = mw * 32, cb = nw * 32;   // 64 rows, 128 d-cols per CTA

    const int laneAr = lane & 15;
    const int laneAk = (lane & 16) >> 1;
    const int laneTr = lane & 15;
    const int laneTd = (lane & 16) >> 1;

    const uint32_t aHb = (uint32_t)__cvta_generic_to_shared(sWhi) +
                         ((rb + laneAr) * KPAD + laneAk) * 2;
    const uint32_t aLb = (uint32_t)__cvta_generic_to_shared(sWlo) +
                         ((rb + laneAr) * KPAD + laneAk) * 2;
    const uint32_t bHb = (uint32_t)__cvta_generic_to_shared(sVhi) +
                         (laneTr * KPAD + cb + laneTd) * 2;
    const uint32_t bLb = (uint32_t)__cvta_generic_to_shared(sVlo) +
                         (laneTr * KPAD + cb + laneTd) * 2;

    const float* Ep = g_E + (size_t)b * SEQ * SEQ;
    float* Wp = outW + (size_t)b * SEQ * SEQ;
    const int g = lane >> 2, q = lane & 3;

    const int erow = tid >> 5;           // + i*8, i<8
    const int ec4  = (tid & 31) * 4;
    const int vrow = tid >> 5;
    const int vc4  = (tid & 31) * 4;

    #pragma unroll 1
    for (int half = 0; half < 2; ++half) {
        const int it = (half == 0) ? itp : 15 - itp;
        const int i0 = it * 128;
        const int i0g = i0 + rh * 64;    // this CTA's first row

        if (tid < 64) sInv[tid] = 1.0f / g_rowsum[b * SEQ + i0g + tid];

        float acc[2][4][4];
        #pragma unroll
        for (int a = 0; a < 2; ++a)
            #pragma unroll
            for (int c = 0; c < 4; ++c)
                #pragma unroll
                for (int d = 0; d < 4; ++d) acc[a][c][d] = 0.f;

        // prefetch first E tile (8 float4/thread)
        float4 epre[8];
        #pragma unroll
        for (int i = 0; i < 8; ++i)
            epre[i] = *(const float4*)(Ep + (size_t)(i0g + erow + i * 8) * SEQ +
                                       it * 128 + ec4);
        __syncthreads();

        for (int jt = it; jt < 16; ++jt) {
            const int j0 = jt * 128;
            // stage normalized weights from prefetch regs; write W
            #pragma unroll
            for (int i = 0; i < 8; ++i) {
                int row = erow + i * 8;
                float4 v = epre[i];
                float inv = sInv[row];
                v.x *= inv; v.y *= inv; v.z *= inv; v.w *= inv;
                *(float4*)(Wp + (size_t)(i0g + row) * SEQ + j0 + ec4) = v;
                uint2 hi, lo; split4(v, hi, lo);
                *(uint2*)(sWhi + row * KPAD + ec4) = hi;
                *(uint2*)(sWlo + row * KPAD + ec4) = lo;
            }
            // stage V tile [128 j][128 d] (natural layout; ldmatrix.trans for B)
            {
                const float* Vp = V + ((size_t)b * SEQ + j0) * DIM;
                #pragma unroll
                for (int i = 0; i < 16; ++i) {
                    int row = vrow + i * 8;
                    float4 v = *(const float4*)(Vp + row * DIM + vc4);
                    uint2 hi, lo; split4(v, hi, lo);
                    *(uint2*)(sVhi + row * KPAD + vc4) = hi;
                    *(uint2*)(sVlo + row * KPAD + vc4) = lo;
                }
            }
            __syncthreads();

            // prefetch next E tile: overlaps with MMA below
            if (jt + 1 < 16) {
                #pragma unroll
                for (int i = 0; i < 8; ++i)
                    epre[i] = *(const float4*)(Ep + (size_t)(i0g + erow + i * 8) * SEQ +
                                               j0 + 128 + ec4);
            }

            #pragma unroll
            for (int ks = 0; ks < 8; ++ks) {
                uint32_t bh[8], bl[8];
                ldsm4t(bh,     bHb + ks * 16 * KPAD * 2);
                ldsm4t(bh + 4, bHb + ks * 16 * KPAD * 2 + 32);   // d-cols +16
                ldsm4t(bl,     bLb + ks * 16 * KPAD * 2);
                ldsm4t(bl + 4, bLb + ks * 16 * KPAD * 2 + 32);
                #pragma unroll
                for (int mf = 0; mf < 2; ++mf) {
                    uint32_t ah[4], al[4];
                    ldsm4(ah, aHb + mf * 16 * KPAD * 2 + ks * 32);
                    ldsm4(al, aLb + mf * 16 * KPAD * 2 + ks * 32);
                    #pragma unroll
                    for (int nf = 0; nf < 4; ++nf) {
                        mma16816(acc[mf][nf], ah, bh[2 * nf], bh[2 * nf + 1]);
                        mma16816(acc[mf][nf], ah, bl[2 * nf], bl[2 * nf + 1]);
                        mma16816(acc[mf][nf], al, bh[2 * nf], bh[2 * nf + 1]);
                    }
                }
            }
            __syncthreads();
        }

        // epilogue: write O for this CTA's 64 rows
        #pragma unroll
        for (int mf = 0; mf < 2; ++mf) {
            int r0 = i0g + rb + mf * 16 + g;
            int r1 = r0 + 8;
            #pragma unroll
            for (int nf = 0; nf < 4; ++nf) {
                int c = cb + nf * 8 + q * 2;
                *(float2*)(outO + ((size_t)b * SEQ + r0) * DIM + c) =
                    make_float2(acc[mf][nf][0], acc[mf][nf][1]);
                *(float2*)(outO + ((size_t)b * SEQ + r1) * DIM + c) =
                    make_float2(acc[mf][nf][2], acc[mf][nf][3]);
            }
        }
        __syncthreads();   // sInv/sW reuse safety for next half
    }
}

extern "C" void kernel_launch(void* const* d_in, const int* in_sizes, int n_in,
                              void* d_out, int out_size)
{
    const float* Q = (const float*)d_in[0];
    const float* K = (const float*)d_in[1];
    const float* V = (const float*)d_in[2];
    float* out  = (float*)d_out;
    float* outO = out;                               // (B,S,D)
    float* outW = out + (size_t)BATCH * SEQ * DIM;   // (B,S,S)

    static int attr_done = 0;
    if (!attr_done) {
        cudaFuncSetAttribute(scores_strip_kernel,
                             cudaFuncAttributeMaxDynamicSharedMemorySize, 139776);
        cudaFuncSetAttribute(output_kernel,
                             cudaFuncAttributeMaxDynamicSharedMemorySize, 104704);
        attr_done = 1;
    }

    scores_strip_kernel<<<dim3(8, 16), NT, 139776>>>(Q, K, outW);
    output_kernel<<<dim3(2, 8, 16), NT, 104704>>>(V, outO, outW);
}